// round 10
// baseline (speedup 1.0000x reference)
#include <cuda_runtime.h>

typedef unsigned long long u64;

#define NQ     10
#define NGEN   4
#define QDEPTH 6
#define MAXB   1024
#define WPB    4   // warps per block

// Parity-of-adjacent-pairs mask for 5-bit k: bit k = popc(k & (k>>1)) & 1.
#define MK_CONST 0x4748B848u
constexpr unsigned mk_check() {
    unsigned m = 0;
    for (int k = 0; k < 32; ++k) {
        int p = 0;
        for (int bb = 0; bb < 4; ++bb) p ^= ((k >> bb) & 1) & ((k >> (bb + 1)) & 1);
        m |= (unsigned)p << k;
    }
    return m;
}
static_assert(mk_check() == MK_CONST, "MK mask mismatch");

// 8 MB inter-kernel scratch: snapshot per batch sample, layout B
// (global index i = k*32 + lane, stored at snap[b*1024 + i]).
__device__ u64 g_snap[MAXB * 1024];

// ---- packed f32x2 helpers (SASS FFMA2 — PTX-only on sm_103a) ----
__device__ __forceinline__ u64 fma2(u64 a, u64 b, u64 c) {
    u64 d; asm("fma.rn.f32x2 %0, %1, %2, %3;" : "=l"(d) : "l"(a), "l"(b), "l"(c)); return d;
}
__device__ __forceinline__ u64 mul2(u64 a, u64 b) {
    u64 d; asm("mul.rn.f32x2 %0, %1, %2;" : "=l"(d) : "l"(a), "l"(b)); return d;
}
__device__ __forceinline__ u64 pack2(float lo, float hi) {
    u64 d; asm("mov.b64 %0, {%1, %2};" : "=l"(d) : "f"(lo), "f"(hi)); return d;
}
__device__ __forceinline__ void unpack2(u64 v, float& lo, float& hi) {
    asm("mov.b64 {%0, %1}, %2;" : "=f"(lo), "=f"(hi) : "l"(v));
}

// ---- RY via 4-op form (init; safe for any angle). phi rotation: c=cos, s=sin ----
template<int M>
__device__ __forceinline__ void ry2(u64 (&v)[32], float c, float s) {
    const u64 cc = pack2(c, c), ss = pack2(s, s), ns = pack2(-s, -s);
    #pragma unroll
    for (int k = 0; k < 32; ++k) if (!(k & M)) {
        const int j = k | M;
        u64 a0 = v[k], a1 = v[j];
        v[k] = fma2(ns, a1, mul2(cc, a0));   // c*a0 - s*a1
        v[j] = fma2(ss, a0, mul2(cc, a1));   // c*a1 + s*a0
    }
}

// ---- RY via shear/lifting: 3 FMA per pair. Rotation phi: nt=-tan(phi/2), sn=sin(phi).
template<int M>
__device__ __forceinline__ void ry2_shear(u64 (&v)[32], u64 nt, u64 sn) {
    #pragma unroll
    for (int k = 0; k < 32; ++k) if (!(k & M)) {
        const int j = k | M;
        u64 a0 = v[k], a1 = v[j];
        a0 = fma2(nt, a1, a0);
        a1 = fma2(sn, a0, a1);
        a0 = fma2(nt, a1, a0);
        v[k] = a0; v[j] = a1;
    }
}

template<int M>
__device__ __forceinline__ void rx2(u64 (&v)[32], float c, float s) {
    #pragma unroll
    for (int k = 0; k < 32; ++k) if (!(k & M)) {
        const int j = k | M;
        float a0r, a0i, a1r, a1i;
        unpack2(v[k], a0r, a0i);
        unpack2(v[j], a1r, a1i);
        v[k] = pack2(fmaf(s, a1i, c * a0r), fmaf(-s, a1r, c * a0i));
        v[j] = pack2(fmaf(s, a0i, c * a1r), fmaf(-s, a0r, c * a1i));
    }
}

template<int M>
__device__ __forceinline__ float exv(const u64 (&v)[32]) {
    u64 acc0 = 0ull, acc1 = 0ull, acc2 = 0ull, acc3 = 0ull;
    #pragma unroll
    for (int k = 0; k < 32; k += 4) {
        acc0 = fma2(v[k + 0], v[(k + 0) ^ M], acc0);
        acc1 = fma2(v[k + 1], v[(k + 1) ^ M], acc1);
        acc2 = fma2(v[k + 2], v[(k + 2) ^ M], acc2);
        acc3 = fma2(v[k + 3], v[(k + 3) ^ M], acc3);
    }
    float l0, h0, l1, h1, l2, h2, l3, h3;
    unpack2(acc0, l0, h0); unpack2(acc1, l1, h1);
    unpack2(acc2, l2, h2); unpack2(acc3, l3, h3);
    return (l0 + h0) + (l1 + h1) + ((l2 + h2) + (l3 + h3));
}

__device__ __forceinline__ void cz_apply(u64 (&v)[32], unsigned sgn) {
    #pragma unroll
    for (int k = 0; k < 32; ++k)
        v[k] ^= (sgn & (1u << k)) ? 0x8000000080000000ull : 0ull;
}

// 32x32 warp transpose through padded smem (stride-34 u64 rows: conflict-free).
__device__ __forceinline__ void transpose(u64 (&v)[32], u64* t, unsigned lane) {
    __syncwarp();
    #pragma unroll
    for (int r = 0; r < 32; r += 2)
        *reinterpret_cast<ulonglong2*>(t + lane * 34u + r) = make_ulonglong2(v[r], v[r + 1]);
    __syncwarp();
    #pragma unroll
    for (int k = 0; k < 32; ++k)
        v[k] = t[k * 34u + lane];
}

// 5 shear-RY gates using precomputed smem consts at indices base..base+4
__device__ __forceinline__ void half5(u64 (&v)[32],
                                      const float* __restrict__ snt,
                                      const float* __restrict__ ssn,
                                      int base) {
    float x;
    u64 nt, sn;
    x = snt[base + 0]; nt = pack2(x, x); x = ssn[base + 0]; sn = pack2(x, x);
    ry2_shear<16>(v, nt, sn);
    x = snt[base + 1]; nt = pack2(x, x); x = ssn[base + 1]; sn = pack2(x, x);
    ry2_shear<8>(v, nt, sn);
    x = snt[base + 2]; nt = pack2(x, x); x = ssn[base + 2]; sn = pack2(x, x);
    ry2_shear<4>(v, nt, sn);
    x = snt[base + 3]; nt = pack2(x, x); x = ssn[base + 3]; sn = pack2(x, x);
    ry2_shear<2>(v, nt, sn);
    x = snt[base + 4]; nt = pack2(x, x); x = ssn[base + 4]; sn = pack2(x, x);
    ry2_shear<1>(v, nt, sn);
}

// ===== Kernel 1: shared init (one warp per batch sample) =====
// Layout A: i = lane*32 + k ; Layout B: i = k*32 + lane.
__global__ void __launch_bounds__(32 * WPB)
qgen_init(const float* __restrict__ noise, int batch)
{
    __shared__ u64   tile[WPB][32 * 34];
    __shared__ float sc[WPB][16], ss_[WPB][16];
    const unsigned lane = threadIdx.x & 31u;
    const unsigned w    = threadIdx.x >> 5;
    const unsigned b    = blockIdx.x * WPB + w;
    if ((int)b >= batch) return;

    // lane-parallel angle precompute: c=cos(0.5*a), s=sin(0.5*a) for 10 angles
    const float* nb = noise + (size_t)b * NQ;
    if (lane < NQ) {
        float s, c;
        __sincosf(0.5f * nb[lane], &s, &c);
        sc[w][lane] = c; ss_[w][lane] = s;
    }
    __syncwarp();

    u64 v[32];
    #pragma unroll
    for (int k = 0; k < 32; ++k) v[k] = 0ull;
    if (lane == 0) v[0] = pack2(1.0f, 0.0f);

    const float* C = sc[w];
    const float* S = ss_[w];
    // layout A: wires 5..9 (M = 16,8,4,2,1)
    ry2<16>(v, C[5], S[5]); rx2<16>(v, C[5], S[5]);
    ry2<8>(v,  C[6], S[6]); rx2<8>(v,  C[6], S[6]);
    ry2<4>(v,  C[7], S[7]); rx2<4>(v,  C[7], S[7]);
    ry2<2>(v,  C[8], S[8]); rx2<2>(v,  C[8], S[8]);
    ry2<1>(v,  C[9], S[9]); rx2<1>(v,  C[9], S[9]);
    transpose(v, tile[w], lane);       // -> layout B
    // wires 0..4
    ry2<16>(v, C[0], S[0]); rx2<16>(v, C[0], S[0]);
    ry2<8>(v,  C[1], S[1]); rx2<8>(v,  C[1], S[1]);
    ry2<4>(v,  C[2], S[2]); rx2<4>(v,  C[2], S[2]);
    ry2<2>(v,  C[3], S[3]); rx2<2>(v,  C[3], S[3]);
    ry2<1>(v,  C[4], S[4]); rx2<1>(v,  C[4], S[4]);

    u64* sp = g_snap + (size_t)b * 1024;
    #pragma unroll
    for (int k = 0; k < 32; ++k)
        sp[k * 32 + lane] = v[k];      // coalesced STG.64
}

// ===== Kernel 2: generator tails (one warp per (b, g)) =====
__global__ void __launch_bounds__(32 * WPB, 4)
qgen_tail(const float* __restrict__ qp,
          float* __restrict__ out, int batch)
{
    __shared__ u64   tile[WPB][32 * 34];
    __shared__ float snt[WPB][64], ssn[WPB][64];
    const unsigned lane = threadIdx.x & 31u;
    const unsigned w    = threadIdx.x >> 5;
    const unsigned wid  = blockIdx.x * WPB + w;
    const unsigned b    = wid >> 2;          // 4 gens of one sample share a block
    const unsigned g    = wid & 3u;
    if ((int)b >= batch) return;
    u64* t = tile[w];

    // lane-parallel shear-const precompute for all 60 angles of generator g.
    // RY(theta) rotates by phi = theta/2: nt = -tan(theta/4), sn = sin(theta/2).
    const float* wg = qp + g * (QDEPTH * NQ);
    {
        float a0 = wg[lane];                       // idx 0..31
        float s4, c4;
        __sincosf(0.25f * a0, &s4, &c4);
        snt[w][lane] = -__fdividef(s4, c4);
        ssn[w][lane] = 2.0f * s4 * c4;
        const int i1 = 32 + (int)lane;             // idx 32..59
        if (i1 < QDEPTH * NQ) {
            float a1 = wg[i1];
            __sincosf(0.25f * a1, &s4, &c4);
            snt[w][i1] = -__fdividef(s4, c4);
            ssn[w][i1] = 2.0f * s4 * c4;
        }
    }
    __syncwarp();
    const float* NT = snt[w];
    const float* SN = ssn[w];

    const unsigned pL   = (__popc(lane & (lane >> 1)) & 1) ? 0xFFFFFFFFu : 0u;
    const unsigned sgnA = MK_CONST ^ pL ^ ((lane & 1u)        ? 0xFFFF0000u : 0u);
    const unsigned sgnB = MK_CONST ^ pL ^ (((lane >> 4) & 1u) ? 0xAAAAAAAAu : 0u);

    // load snapshot (layout B); coalesced, L1-shared across the block's 4 warps
    u64 v[32];
    const u64* sp = g_snap + (size_t)b * 1024;
    #pragma unroll
    for (int k = 0; k < 32; ++k)
        v[k] = sp[k * 32 + lane];

    #pragma unroll
    for (int l = 0; l < QDEPTH; l += 2) {
        const int w0 = l * NQ;
        half5(v, NT, SN, w0 + 0);      // layout B: wires 0..4
        transpose(v, t, lane);         // -> A
        half5(v, NT, SN, w0 + 5);      // wires 5..9
        cz_apply(v, sgnA);
        const int w1 = w0 + NQ;
        half5(v, NT, SN, w1 + 5);      // layout A: wires 5..9
        transpose(v, t, lane);         // -> B
        half5(v, NT, SN, w1 + 0);      // wires 0..4
        cz_apply(v, sgnB);
    }

    float e[10];
    e[0] = exv<16>(v); e[1] = exv<8>(v); e[2] = exv<4>(v);   // layout B: wires 0..4
    e[3] = exv<2>(v);  e[4] = exv<1>(v);
    transpose(v, t, lane);                                    // -> A
    e[5] = exv<16>(v); e[6] = exv<8>(v); e[7] = exv<4>(v);   // wires 5..9
    e[8] = exv<2>(v);  e[9] = exv<1>(v);

    #pragma unroll
    for (int q = 0; q < 10; ++q) {
        float a = e[q];
        #pragma unroll
        for (int o = 16; o; o >>= 1) a += __shfl_xor_sync(0xffffffffu, a, o);
        e[q] = a;
    }
    if (lane == 0) {
        float* ob = out + (size_t)b * (NGEN * NQ) + (size_t)g * NQ;
        #pragma unroll
        for (int q = 0; q < 10; ++q) ob[q] = e[q];
    }
}

extern "C" void kernel_launch(void* const* d_in, const int* in_sizes, int n_in,
                              void* d_out, int out_size) {
    const float* noise = (const float*)d_in[0];   // (BATCH, NQ) fp32
    const float* qp    = (const float*)d_in[1];   // (NGEN, QDEPTH, NQ) fp32
    float* out = (float*)d_out;                   // (BATCH, NGEN*NQ) fp32

    int batch = in_sizes[0] / NQ;
    if (batch > MAXB) batch = MAXB;

    int init_blocks = (batch + WPB - 1) / WPB;
    qgen_init<<<init_blocks, 32 * WPB>>>(noise, batch);

    int tail_warps  = batch * NGEN;
    int tail_blocks = (tail_warps + WPB - 1) / WPB;
    qgen_tail<<<tail_blocks, 32 * WPB>>>(qp, out, batch);
}